// round 15
// baseline (speedup 1.0000x reference)
#include <cuda_runtime.h>
#include <cuda_bf16.h>
#include <math.h>
#include <stdint.h>

#define NMAX 100000
#define C 128
#define C2 256
#define PP 64
#define DIST_TH 0.1f

// ---------------- scratch (device globals: allocation-free rule) --------------
__device__ __nv_bfloat16 g_fh[(size_t)NMAX * C];
__device__ __nv_bfloat16 g_fm[(size_t)NMAX * C];
__device__ __nv_bfloat16 g_hh[(size_t)NMAX * C2];
__device__ __nv_bfloat16 g_hm[(size_t)NMAX * C2];
__device__ __nv_bfloat16 g_gh[(size_t)NMAX * C];   // gathered h2 splits (compacted)
__device__ __nv_bfloat16 g_gm[(size_t)NMAX * C];
__device__ float g_h2[(size_t)NMAX * C];
__device__ float g_a [(size_t)NMAX * C];           // compacted att activations
__device__ __nv_bfloat16 g_w1h[C2 * C], g_w1m[C2 * C];   // [N=256][K=128]
__device__ __nv_bfloat16 g_w2h[C * C2], g_w2m[C * C2];   // [N=128][K=256]
__device__ __nv_bfloat16 g_wah[C * C],  g_wam[C * C];    // [N=128][K=128]
__device__ int   g_idx[NMAX];
__device__ unsigned long long g_maskArr[NMAX];
__device__ int   g_cnt;
__device__ unsigned int g_maxU[C];
__device__ float g_num_on [PP * C];
__device__ float g_den_on [PP * C];
__device__ float g_num_off[PP * C];
__device__ float g_den_off[PP * C];

__device__ __forceinline__ unsigned int fkey(float f) {
    unsigned int u = __float_as_uint(f);
    return (u & 0x80000000u) ? ~u : (u | 0x80000000u);
}
__device__ __forceinline__ float funkey(unsigned int k) {
    unsigned int u = (k & 0x80000000u) ? (k & 0x7fffffffu) : ~k;
    return __uint_as_float(u);
}
__device__ __forceinline__ uint32_t pk2(__nv_bfloat16 a, __nv_bfloat16 b) {
    return (uint32_t)__bfloat16_as_ushort(a) | ((uint32_t)__bfloat16_as_ushort(b) << 16);
}
__device__ __forceinline__ void split2(float v, __nv_bfloat16& h, __nv_bfloat16& m) {
    h = __float2bfloat16(v);
    m = __float2bfloat16(v - __bfloat162float(h));
}
__device__ __forceinline__ uint32_t smem_u32(const void* p) {
    uint32_t a;
    asm("{ .reg .u64 t; cvta.to.shared.u64 t, %1; cvt.u32.u64 %0, t; }" : "=r"(a) : "l"(p));
    return a;
}
#define CP16(dst, src, sz) \
    asm volatile("cp.async.cg.shared.global [%0], [%1], 16, %2;" \
                 :: "r"(dst), "l"(src), "r"(sz) : "memory")
#define CP_COMMIT() asm volatile("cp.async.commit_group;" ::: "memory")
#define CP_WAIT1() asm volatile("cp.async.wait_group 1;" ::: "memory")
#define CP_WAIT0() asm volatile("cp.async.wait_group 0;" ::: "memory")

// ---------------- init ----------------
__global__ void init_kernel() {
    int t = blockIdx.x * blockDim.x + threadIdx.x;
    int stride = gridDim.x * blockDim.x;
    if (t == 0) g_cnt = 0;
    if (t < C) g_maxU[t] = 0u;
    for (int i = t; i < PP * C; i += stride) {
        g_num_on[i] = 0.f; g_den_on[i] = 0.f;
        g_num_off[i] = 0.f; g_den_off[i] = 0.f;
    }
}

// ---------------- split kernels ----------------
__global__ void split_feat_kernel(const float* __restrict__ src,
                                  __nv_bfloat16* __restrict__ dh,
                                  __nv_bfloat16* __restrict__ dm, int n4) {
    int i = blockIdx.x * blockDim.x + threadIdx.x;
    if (i >= n4) return;
    float4 f = ((const float4*)src)[i];
    __nv_bfloat16 h[4], m[4];
    split2(f.x, h[0], m[0]);
    split2(f.y, h[1], m[1]);
    split2(f.z, h[2], m[2]);
    split2(f.w, h[3], m[3]);
    ((uint2*)dh)[i] = make_uint2(pk2(h[0], h[1]), pk2(h[2], h[3]));
    ((uint2*)dm)[i] = make_uint2(pk2(m[0], m[1]), pk2(m[2], m[3]));
}

// all three weight transposes+splits in ONE launch
__global__ void split_w_all_kernel(const float* __restrict__ W1,
                                   const float* __restrict__ W2,
                                   const float* __restrict__ Wa) {
    int id = blockIdx.x * blockDim.x + threadIdx.x;
    const int t1 = C * C2, t2 = t1 + C2 * C, t3 = t2 + C * C;
    const float* src; __nv_bfloat16 *dh, *dm; int K, N, lid;
    if (id < t1)      { src = W1; dh = g_w1h; dm = g_w1m; K = C;  N = C2; lid = id; }
    else if (id < t2) { src = W2; dh = g_w2h; dm = g_w2m; K = C2; N = C;  lid = id - t1; }
    else if (id < t3) { src = Wa; dh = g_wah; dm = g_wam; K = C;  N = C;  lid = id - t2; }
    else return;
    int k = lid / N, n = lid % N;
    __nv_bfloat16 h, m;
    split2(src[lid], h, m);
    dh[n * K + k] = h;
    dm[n * K + k] = m;
}

__global__ void gather_split_kernel(const float* __restrict__ h2) {
    int cnt = g_cnt;
    int total = cnt * C;
    int stride = gridDim.x * blockDim.x;
    for (int idx = blockIdx.x * blockDim.x + threadIdx.x; idx < total; idx += stride) {
        int i = idx >> 7, c = idx & 127;
        float v = h2[(size_t)g_idx[i] * C + c];
        __nv_bfloat16 h, m;
        split2(v, h, m);
        g_gh[idx] = h; g_gm[idx] = m;
    }
}

// ---------------- fused-term cp.async mma GEMM, 128x128 tile -----------------
// K-chunk 32; per chunk load Ah/Am/Bh/Bm tiles once, issue all 3 term-combos.
// Tiles: 128 rows x 32 bf16, row pitch 80B (conflict-free, no swizzle).
// smem/stage = 4*10240 = 40960; double-buffered = 81920 (+2KB epi).
// MODE 0: FC1 (epi: relu(v*s+b) -> write h splits bf16 x2)
// MODE 1: FC2 (epi: relu(v*s+b) -> h2 fp32 + fused logit = h2@W3+b3)
// MODE 2: ATT (A = compacted h2 splits; epi: write a fp32 + per-col max)
#define RPITCH 80
#define TILEB  10240
#define STAGEB 40960
template<int MODE>
__global__ __launch_bounds__(256, 2)
void mma_gemm(const __nv_bfloat16* __restrict__ Ah, const __nv_bfloat16* __restrict__ Am,
              const __nv_bfloat16* __restrict__ Bh, const __nv_bfloat16* __restrict__ Bm,
              const float* __restrict__ scale, const float* __restrict__ bias,
              const float* __restrict__ W3, const float* __restrict__ b3,
              float* __restrict__ logitOut,
              __nv_bfloat16* __restrict__ Oh, __nv_bfloat16* __restrict__ Om,
              float* __restrict__ Of,
              int M, int Ks, int Nn)
{
    extern __shared__ __align__(1024) char sm[];
    char* sEpi = sm + 2 * STAGEB;
    float* s_s  = (float*)sEpi;
    float* s_b  = s_s + 128;
    float* s_w3 = s_b + 128;
    unsigned int* s_red = (unsigned int*)(s_w3 + 128);

    const int tid = threadIdx.x;
    const int wid = tid >> 5, lane = tid & 31;
    const int warpm = wid & 3, warpn = wid >> 2;
    const int gi = lane >> 2, ti = lane & 3;
    const int m0 = blockIdx.x * 128, n0 = blockIdx.y * 128;

    int Meff = M;
    if (MODE == 2) {
        Meff = g_cnt;
        if (m0 >= Meff) return;
    }

    if (tid < 128) {
        if (MODE != 2) { s_s[tid] = scale[n0 + tid]; s_b[tid] = bias[n0 + tid]; }
        if (MODE == 1) { s_w3[tid] = W3[tid]; s_red[tid] = 0u; }
        if (MODE == 2) { s_red[tid] = 0u; }
    }

    float acc[2][8][4];
#pragma unroll
    for (int i = 0; i < 2; i++)
#pragma unroll
        for (int j = 0; j < 8; j++)
#pragma unroll
            for (int q = 0; q < 4; q++) acc[i][j][q] = 0.f;

    const int nchunks = Ks >> 5;          // K-chunks of 32
    const uint32_t smu = smem_u32(sm);

    // cp.async geometry: thread -> row (tid>>1), 2 consecutive 16B chunks (tid&1)*2
    const int ldRow = tid >> 1;
    const int ldJ = (tid & 1) * 2;        // chunk 16B index base within 64B of data
    const int grA = m0 + ldRow;
    const int okA = (grA < Meff) ? 16 : 0;
    const size_t aOffRow = (size_t)(okA ? grA : 0) * Ks;
    const size_t bOffRow = (size_t)(n0 + ldRow) * Ks;
    const uint32_t dstRow = (uint32_t)ldRow * RPITCH + (uint32_t)ldJ * 16;

    auto issue = [&](int ci) {
        int kc = ci << 5;
        uint32_t st = smu + (uint32_t)(ci & 1) * STAGEB + dstRow;
        const char* pAh = (const char*)(Ah + aOffRow + kc + ldJ * 8);
        const char* pAm = (const char*)(Am + aOffRow + kc + ldJ * 8);
        const char* pBh = (const char*)(Bh + bOffRow + kc + ldJ * 8);
        const char* pBm = (const char*)(Bm + bOffRow + kc + ldJ * 8);
        CP16(st,              pAh,      okA);
        CP16(st + 16,         pAh + 16, okA);
        CP16(st + TILEB,      pAm,      okA);
        CP16(st + TILEB + 16, pAm + 16, okA);
        CP16(st + 2 * TILEB,      pBh,      16);
        CP16(st + 2 * TILEB + 16, pBh + 16, 16);
        CP16(st + 3 * TILEB,      pBm,      16);
        CP16(st + 3 * TILEB + 16, pBm + 16, 16);
        CP_COMMIT();
    };

    issue(0);
    for (int ci = 0; ci < nchunks; ci++) {
        if (ci + 1 < nchunks) { issue(ci + 1); CP_WAIT1(); }
        else                  { CP_WAIT0(); }
        __syncthreads();

        const char* bS = sm + (ci & 1) * STAGEB;
        const char* bAh = bS;
        const char* bAm = bS + TILEB;
        const char* bBh = bS + 2 * TILEB;
        const char* bBm = bS + 3 * TILEB;

#pragma unroll
        for (int kk = 0; kk < 32; kk += 16) {
            const uint32_t kb = (uint32_t)kk * 2 + ti * 4;
            uint32_t aH[2][4], aM[2][4];
#pragma unroll
            for (int mt = 0; mt < 2; mt++) {
                uint32_t r0 = (uint32_t)(warpm * 32 + mt * 16 + gi) * RPITCH + kb;
                aH[mt][0] = *(const uint32_t*)(bAh + r0);
                aH[mt][1] = *(const uint32_t*)(bAh + r0 + 8 * RPITCH);
                aH[mt][2] = *(const uint32_t*)(bAh + r0 + 16);
                aH[mt][3] = *(const uint32_t*)(bAh + r0 + 8 * RPITCH + 16);
                aM[mt][0] = *(const uint32_t*)(bAm + r0);
                aM[mt][1] = *(const uint32_t*)(bAm + r0 + 8 * RPITCH);
                aM[mt][2] = *(const uint32_t*)(bAm + r0 + 16);
                aM[mt][3] = *(const uint32_t*)(bAm + r0 + 8 * RPITCH + 16);
            }
            // B-high split: combos HH (aH x bH) and MH (aM x bH)
            {
                uint32_t bfr[8][2];
#pragma unroll
                for (int nt = 0; nt < 8; nt++) {
                    uint32_t r0 = (uint32_t)(warpn * 64 + nt * 8 + gi) * RPITCH + kb;
                    bfr[nt][0] = *(const uint32_t*)(bBh + r0);
                    bfr[nt][1] = *(const uint32_t*)(bBh + r0 + 16);
                }
#pragma unroll
                for (int mt = 0; mt < 2; mt++)
#pragma unroll
                    for (int nt = 0; nt < 8; nt++) {
                        asm volatile(
                            "mma.sync.aligned.m16n8k16.row.col.f32.bf16.bf16.f32 "
                            "{%0,%1,%2,%3}, {%4,%5,%6,%7}, {%8,%9}, {%0,%1,%2,%3};"
                            : "+f"(acc[mt][nt][0]), "+f"(acc[mt][nt][1]),
                              "+f"(acc[mt][nt][2]), "+f"(acc[mt][nt][3])
                            : "r"(aH[mt][0]), "r"(aH[mt][1]),
                              "r"(aH[mt][2]), "r"(aH[mt][3]),
                              "r"(bfr[nt][0]), "r"(bfr[nt][1]));
                        asm volatile(
                            "mma.sync.aligned.m16n8k16.row.col.f32.bf16.bf16.f32 "
                            "{%0,%1,%2,%3}, {%4,%5,%6,%7}, {%8,%9}, {%0,%1,%2,%3};"
                            : "+f"(acc[mt][nt][0]), "+f"(acc[mt][nt][1]),
                              "+f"(acc[mt][nt][2]), "+f"(acc[mt][nt][3])
                            : "r"(aM[mt][0]), "r"(aM[mt][1]),
                              "r"(aM[mt][2]), "r"(aM[mt][3]),
                              "r"(bfr[nt][0]), "r"(bfr[nt][1]));
                    }
            }
            // B-mid split: combo HM (aH x bM)
            {
                uint32_t bfr[8][2];
#pragma unroll
                for (int nt = 0; nt < 8; nt++) {
                    uint32_t r0 = (uint32_t)(warpn * 64 + nt * 8 + gi) * RPITCH + kb;
                    bfr[nt][0] = *(const uint32_t*)(bBm + r0);
                    bfr[nt][1] = *(const uint32_t*)(bBm + r0 + 16);
                }
#pragma unroll
                for (int mt = 0; mt < 2; mt++)
#pragma unroll
                    for (int nt = 0; nt < 8; nt++) {
                        asm volatile(
                            "mma.sync.aligned.m16n8k16.row.col.f32.bf16.bf16.f32 "
                            "{%0,%1,%2,%3}, {%4,%5,%6,%7}, {%8,%9}, {%0,%1,%2,%3};"
                            : "+f"(acc[mt][nt][0]), "+f"(acc[mt][nt][1]),
                              "+f"(acc[mt][nt][2]), "+f"(acc[mt][nt][3])
                            : "r"(aH[mt][0]), "r"(aH[mt][1]),
                              "r"(aH[mt][2]), "r"(aH[mt][3]),
                              "r"(bfr[nt][0]), "r"(bfr[nt][1]));
                    }
            }
        }
        __syncthreads();   // protect stage (ci&1) before issue(ci+2) overwrites it
    }

    // ---------------- epilogue ----------------
    float ls[2][2] = {{0.f, 0.f}, {0.f, 0.f}};
    float cmax0[8], cmax1[8];
    if (MODE == 2) {
#pragma unroll
        for (int nt = 0; nt < 8; nt++) { cmax0[nt] = -INFINITY; cmax1[nt] = -INFINITY; }
    }

#pragma unroll
    for (int mt = 0; mt < 2; mt++) {
#pragma unroll
        for (int half = 0; half < 2; half++) {
            int rowL = warpm * 32 + mt * 16 + gi + half * 8;
            int row = m0 + rowL;
            bool vrow = row < Meff;
#pragma unroll
            for (int nt = 0; nt < 8; nt++) {
                int colL = warpn * 64 + nt * 8 + 2 * ti;
                float c0 = acc[mt][nt][2 * half];
                float c1 = acc[mt][nt][2 * half + 1];
                if (MODE != 2) {
                    c0 = fmaxf(fmaf(c0, s_s[colL], s_b[colL]), 0.f);
                    c1 = fmaxf(fmaf(c1, s_s[colL + 1], s_b[colL + 1]), 0.f);
                }
                if (MODE == 0) {
                    if (vrow) {
                        __nv_bfloat16 h0, m0b, h1, m1;
                        split2(c0, h0, m0b);
                        split2(c1, h1, m1);
                        size_t off = (size_t)row * Nn + n0 + colL;
                        *(uint32_t*)(Oh + off) = pk2(h0, h1);
                        *(uint32_t*)(Om + off) = pk2(m0b, m1);
                    }
                } else if (MODE == 1) {
                    if (vrow)
                        *(float2*)(Of + (size_t)row * 128 + colL) = make_float2(c0, c1);
                    ls[mt][half] = fmaf(c0, s_w3[colL], ls[mt][half]);
                    ls[mt][half] = fmaf(c1, s_w3[colL + 1], ls[mt][half]);
                } else {
                    if (vrow) {
                        *(float2*)(Of + (size_t)row * 128 + colL) = make_float2(c0, c1);
                        cmax0[nt] = fmaxf(cmax0[nt], c0);
                        cmax1[nt] = fmaxf(cmax1[nt], c1);
                    }
                }
            }
        }
    }

    if (MODE == 1) {
#pragma unroll
        for (int mt = 0; mt < 2; mt++) {
            atomicAdd((float*)&s_red[warpm * 32 + mt * 16 + gi], ls[mt][0]);
            atomicAdd((float*)&s_red[warpm * 32 + mt * 16 + gi + 8], ls[mt][1]);
        }
        __syncthreads();
        if (tid < 128) {
            int row = m0 + tid;
            if (row < Meff)
                logitOut[row] = __uint_as_float(s_red[tid]) + b3[0];
        }
    } else if (MODE == 2) {
#pragma unroll
        for (int nt = 0; nt < 8; nt++) {
            int colL = warpn * 64 + nt * 8 + 2 * ti;
            if (cmax0[nt] > -INFINITY) atomicMax(&s_red[colL], fkey(cmax0[nt]));
            if (cmax1[nt] > -INFINITY) atomicMax(&s_red[colL + 1], fkey(cmax1[nt]));
        }
        __syncthreads();
        if (tid < 128 && s_red[tid] != 0u)
            atomicMax(&g_maxU[tid], s_red[tid]);
    }
}

// ---------------- mask pass: compact hit points ------------------------------
__global__ void mask_kernel(const float* __restrict__ xyz,
                            const float* __restrict__ pc,
                            const float* __restrict__ pn,
                            const float* __restrict__ pmn,
                            const float* __restrict__ pmx, int M)
{
    __shared__ float s_n0[PP], s_n1[PP], s_n2[PP], s_off[PP];
    __shared__ float s_mn0[PP], s_mn1[PP], s_mx0[PP], s_mx1[PP];
    int t = threadIdx.x;
    if (t < PP) {
        float a0 = pn[t * 3], a1 = pn[t * 3 + 1], a2 = pn[t * 3 + 2];
        s_n0[t] = a0; s_n1[t] = a1; s_n2[t] = a2;
        s_off[t] = pc[t * 3] * a0 + pc[t * 3 + 1] * a1 + pc[t * 3 + 2] * a2;
        s_mn0[t] = pmn[t * 3]; s_mn1[t] = pmn[t * 3 + 1];
        s_mx0[t] = pmx[t * 3]; s_mx1[t] = pmx[t * 3 + 1];
    }
    __syncthreads();
    int n = blockIdx.x * blockDim.x + t;
    if (n >= M) return;
    float x = xyz[n * 3], y = xyz[n * 3 + 1], z = xyz[n * 3 + 2];
    unsigned long long mask = 0ull;
#pragma unroll
    for (int p = 0; p < PP; p++) {
        float proj = x * s_n0[p] + y * s_n1[p] + z * s_n2[p];
        bool hit = (fabsf(proj - s_off[p]) < DIST_TH) &&
                   (x >= s_mn0[p]) && (x < s_mx0[p]) &&
                   (y >= s_mn1[p]) && (y < s_mx1[p]);
        if (hit) mask |= (1ull << p);
    }
    if (mask) {
        int pos = atomicAdd(&g_cnt, 1);
        g_idx[pos] = n;
        g_maskArr[pos] = mask;
    }
}

// ---------------- pooling scatter over compacted points ----------------------
__global__ void pool2_kernel(const float* __restrict__ logit)
{
    __shared__ float s_amax[C];
    if (threadIdx.x < C) s_amax[threadIdx.x] = funkey(g_maxU[threadIdx.x]);
    __syncthreads();
    int cnt = g_cnt;
    int stride = gridDim.x * blockDim.x;
    for (int i = blockIdx.x * blockDim.x + threadIdx.x; i < cnt; i += stride) {
        int n = g_idx[i];
        unsigned long long mask = g_maskArr[i];
        bool on = logit[n] > 0.0f;
        float* numB = on ? g_num_on : g_num_off;
        float* denB = on ? g_den_on : g_den_off;
        const float* ar = g_a + (size_t)i * C;
        const float* hr = g_h2 + (size_t)n * C;
        for (int c = 0; c < C; c += 4) {
            float4 a4 = *(const float4*)(ar + c);
            float4 h4 = *(const float4*)(hr + c);
            float e0 = expf(a4.x - s_amax[c + 0]);
            float e1 = expf(a4.y - s_amax[c + 1]);
            float e2 = expf(a4.z - s_amax[c + 2]);
            float e3 = expf(a4.w - s_amax[c + 3]);
            unsigned long long mm = mask;
            while (mm) {
                int p = __ffsll(mm) - 1;
                mm &= mm - 1;
                float* dn = denB + p * C + c;
                float* nm = numB + p * C + c;
                atomicAdd(dn + 0, e0); atomicAdd(dn + 1, e1);
                atomicAdd(dn + 2, e2); atomicAdd(dn + 3, e3);
                atomicAdd(nm + 0, e0 * h4.x); atomicAdd(nm + 1, e1 * h4.y);
                atomicAdd(nm + 2, e2 * h4.z); atomicAdd(nm + 3, e3 * h4.w);
            }
        }
    }
}

// ---------------- finalize: agg -> relu(agg@Wm+bm), concat ori --------------
__global__ void finalize_kernel(const float* __restrict__ Wm,
                                const float* __restrict__ bm,
                                const float* __restrict__ pc,
                                const float* __restrict__ pn,
                                const float* __restrict__ pmn,
                                const float* __restrict__ pmx,
                                float* __restrict__ out, int M)
{
    int p = blockIdx.x;     // 64
    int c = threadIdx.x;    // 128
    __shared__ float aggOn[C], aggOff[C];
    aggOn[c]  = g_num_on [p * C + c] / (g_den_on [p * C + c] + 1e-9f);
    aggOff[c] = g_num_off[p * C + c] / (g_den_off[p * C + c] + 1e-9f);
    __syncthreads();
    float so = 0.f, sf = 0.f;
#pragma unroll 8
    for (int k = 0; k < C; k++) {
        float w = Wm[k * C + c];
        so = fmaf(aggOn[k], w, so);
        sf = fmaf(aggOff[k], w, sf);
    }
    float bb = bm[c];
    float* onRow  = out + M + (size_t)p * (C + 12);
    float* offRow = out + M + (size_t)PP * (C + 12) + (size_t)p * (C + 12);
    onRow[c]  = fmaxf(so + bb, 0.f);
    offRow[c] = fmaxf(sf + bb, 0.f);
    if (c < 12) {
        int axis = c % 3, grp = c / 3;
        const float* src = (grp == 0) ? pc : (grp == 1) ? pn : (grp == 2) ? pmn : pmx;
        float v = src[p * 3 + axis];
        onRow[C + c] = v;
        offRow[C + c] = v;
    }
}

// ---------------- launch ----------------
extern "C" void kernel_launch(void* const* d_in, const int* in_sizes, int n_in,
                              void* d_out, int out_size)
{
    const float* feature = (const float*)d_in[0];
    const float* xyz     = (const float*)d_in[1];
    const float* pc      = (const float*)d_in[2];
    const float* pn      = (const float*)d_in[3];
    const float* pmn     = (const float*)d_in[4];
    const float* pmx     = (const float*)d_in[5];
    const float* W1      = (const float*)d_in[6];
    const float* s1      = (const float*)d_in[7];
    const float* b1      = (const float*)d_in[8];
    const float* W2      = (const float*)d_in[9];
    const float* s2      = (const float*)d_in[10];
    const float* b2      = (const float*)d_in[11];
    const float* W3      = (const float*)d_in[12];
    const float* b3      = (const float*)d_in[13];
    const float* Wa      = (const float*)d_in[14];
    const float* Wm      = (const float*)d_in[15];
    const float* bm      = (const float*)d_in[16];

    int M = in_sizes[1] / 3;            // N = 100000
    float* out = (float*)d_out;

    __nv_bfloat16 *fh, *fm, *hh, *hm, *gh, *gm;
    __nv_bfloat16 *w1h, *w1m, *w2h, *w2m, *wah, *wam;
    float *h2P, *aP;
    cudaGetSymbolAddress((void**)&fh, g_fh);
    cudaGetSymbolAddress((void**)&fm, g_fm);
    cudaGetSymbolAddress((void**)&hh, g_hh);
    cudaGetSymbolAddress((void**)&hm, g_hm);
    cudaGetSymbolAddress((void**)&gh, g_gh);
    cudaGetSymbolAddress((void**)&gm, g_gm);
    cudaGetSymbolAddress((void**)&w1h, g_w1h);
    cudaGetSymbolAddress((void**)&w1m, g_w1m);
    cudaGetSymbolAddress((void**)&w2h, g_w2h);
    cudaGetSymbolAddress((void**)&w2m, g_w2m);
    cudaGetSymbolAddress((void**)&wah, g_wah);
    cudaGetSymbolAddress((void**)&wam, g_wam);
    cudaGetSymbolAddress((void**)&h2P, g_h2);
    cudaGetSymbolAddress((void**)&aP,  g_a);

    const int SMEM = 2 * STAGEB + 2048;    // 83968
    cudaFuncSetAttribute(mma_gemm<0>, cudaFuncAttributeMaxDynamicSharedMemorySize, SMEM);
    cudaFuncSetAttribute(mma_gemm<1>, cudaFuncAttributeMaxDynamicSharedMemorySize, SMEM);
    cudaFuncSetAttribute(mma_gemm<2>, cudaFuncAttributeMaxDynamicSharedMemorySize, SMEM);

    int gx = (M + 127) / 128;           // 782

    init_kernel<<<32, 256>>>();
    mask_kernel<<<(M + 255) / 256, 256>>>(xyz, pc, pn, pmn, pmx, M);
    split_feat_kernel<<<(M * C / 4 + 255) / 256, 256>>>(feature, fh, fm, M * C / 4);
    split_w_all_kernel<<<(2 * C * C2 + C * C + 255) / 256, 256>>>(W1, W2, Wa);

    // FC1: h = relu((feature@W1)*s1+b1) -> h splits   [M,128]x[128,256]
    mma_gemm<0><<<dim3(gx, 2), 256, SMEM>>>(fh, fm, w1h, w1m,
                                            s1, b1, nullptr, nullptr, nullptr,
                                            hh, hm, nullptr, M, C, C2);
    // FC2: h2 = relu((h@W2)*s2+b2) fp32 + fused logit -> out[0..M)
    mma_gemm<1><<<dim3(gx, 1), 256, SMEM>>>(hh, hm, w2h, w2m,
                                            s2, b2, W3, b3, out,
                                            nullptr, nullptr, h2P, M, C2, C);
    // gather+split h2 rows for masked points
    gather_split_kernel<<<256, 256>>>(h2P);
    // ATT: a = h2_masked @ Wa + per-channel max over masked rows
    mma_gemm<2><<<dim3(gx, 1), 256, SMEM>>>(gh, gm, wah, wam,
                                            nullptr, nullptr, nullptr, nullptr, nullptr,
                                            nullptr, nullptr, aP, M, C, C);
    // sparse masked softmax pooling scatter
    pool2_kernel<<<256, 256>>>(out);
    // tiny per-plane GEMM + ori concat
    finalize_kernel<<<PP, 128>>>(Wm, bm, pc, pn, pmn, pmx, out, M);
}

// round 16
// speedup vs baseline: 1.1235x; 1.1235x over previous
#include <cuda_runtime.h>
#include <cuda_bf16.h>
#include <math.h>
#include <stdint.h>

#define NMAX 100000
#define C 128
#define C2 256
#define PP 64
#define DIST_TH 0.1f

// ---------------- scratch (device globals: allocation-free rule) --------------
__device__ __nv_bfloat16 g_fh[(size_t)NMAX * C];
__device__ __nv_bfloat16 g_fm[(size_t)NMAX * C];
__device__ __nv_bfloat16 g_hh[(size_t)NMAX * C2];
__device__ __nv_bfloat16 g_hm[(size_t)NMAX * C2];
__device__ __nv_bfloat16 g_gh[(size_t)NMAX * C];   // gathered h2 splits (compacted)
__device__ __nv_bfloat16 g_gm[(size_t)NMAX * C];
__device__ float g_h2[(size_t)NMAX * C];
__device__ float g_a [(size_t)NMAX * C];           // compacted att activations
__device__ __nv_bfloat16 g_w1h[C2 * C], g_w1m[C2 * C];   // [N=256][K=128]
__device__ __nv_bfloat16 g_w2h[C * C2], g_w2m[C * C2];   // [N=128][K=256]
__device__ __nv_bfloat16 g_wah[C * C],  g_wam[C * C];    // [N=128][K=128]
__device__ int   g_idx[NMAX];
__device__ unsigned long long g_maskArr[NMAX];
__device__ int   g_cnt;
__device__ unsigned int g_maxU[C];
__device__ float g_num_on [PP * C];
__device__ float g_den_on [PP * C];
__device__ float g_num_off[PP * C];
__device__ float g_den_off[PP * C];

__device__ __forceinline__ unsigned int fkey(float f) {
    unsigned int u = __float_as_uint(f);
    return (u & 0x80000000u) ? ~u : (u | 0x80000000u);
}
__device__ __forceinline__ float funkey(unsigned int k) {
    unsigned int u = (k & 0x80000000u) ? (k & 0x7fffffffu) : ~k;
    return __uint_as_float(u);
}
__device__ __forceinline__ uint32_t pk2(__nv_bfloat16 a, __nv_bfloat16 b) {
    return (uint32_t)__bfloat16_as_ushort(a) | ((uint32_t)__bfloat16_as_ushort(b) << 16);
}
__device__ __forceinline__ void split2(float v, __nv_bfloat16& h, __nv_bfloat16& m) {
    h = __float2bfloat16(v);
    m = __float2bfloat16(v - __bfloat162float(h));
}
__device__ __forceinline__ uint32_t smem_u32(const void* p) {
    uint32_t a;
    asm("{ .reg .u64 t; cvta.to.shared.u64 t, %1; cvt.u32.u64 %0, t; }" : "=r"(a) : "l"(p));
    return a;
}
#define CP16(dst, src, sz) \
    asm volatile("cp.async.cg.shared.global [%0], [%1], 16, %2;" \
                 :: "r"(dst), "l"(src), "r"(sz) : "memory")
#define CP_COMMIT() asm volatile("cp.async.commit_group;" ::: "memory")
#define CP_WAIT1() asm volatile("cp.async.wait_group 1;" ::: "memory")
#define CP_WAIT0() asm volatile("cp.async.wait_group 0;" ::: "memory")
#define LDSM4(r0, r1, r2, r3, addr) \
    asm volatile("ldmatrix.sync.aligned.m8n8.x4.shared.b16 {%0,%1,%2,%3}, [%4];" \
                 : "=r"(r0), "=r"(r1), "=r"(r2), "=r"(r3) : "r"(addr))

// ---------------- init ----------------
__global__ void init_kernel() {
    int t = blockIdx.x * blockDim.x + threadIdx.x;
    int stride = gridDim.x * blockDim.x;
    if (t == 0) g_cnt = 0;
    if (t < C) g_maxU[t] = 0u;
    for (int i = t; i < PP * C; i += stride) {
        g_num_on[i] = 0.f; g_den_on[i] = 0.f;
        g_num_off[i] = 0.f; g_den_off[i] = 0.f;
    }
}

// ---------------- split kernels ----------------
__global__ void split_feat_kernel(const float* __restrict__ src,
                                  __nv_bfloat16* __restrict__ dh,
                                  __nv_bfloat16* __restrict__ dm, int n4) {
    int i = blockIdx.x * blockDim.x + threadIdx.x;
    if (i >= n4) return;
    float4 f = ((const float4*)src)[i];
    __nv_bfloat16 h[4], m[4];
    split2(f.x, h[0], m[0]);
    split2(f.y, h[1], m[1]);
    split2(f.z, h[2], m[2]);
    split2(f.w, h[3], m[3]);
    ((uint2*)dh)[i] = make_uint2(pk2(h[0], h[1]), pk2(h[2], h[3]));
    ((uint2*)dm)[i] = make_uint2(pk2(m[0], m[1]), pk2(m[2], m[3]));
}

__global__ void split_w_all_kernel(const float* __restrict__ W1,
                                   const float* __restrict__ W2,
                                   const float* __restrict__ Wa) {
    int id = blockIdx.x * blockDim.x + threadIdx.x;
    const int t1 = C * C2, t2 = t1 + C2 * C, t3 = t2 + C * C;
    const float* src; __nv_bfloat16 *dh, *dm; int K, N, lid;
    if (id < t1)      { src = W1; dh = g_w1h; dm = g_w1m; K = C;  N = C2; lid = id; }
    else if (id < t2) { src = W2; dh = g_w2h; dm = g_w2m; K = C2; N = C;  lid = id - t1; }
    else if (id < t3) { src = Wa; dh = g_wah; dm = g_wam; K = C;  N = C;  lid = id - t2; }
    else return;
    int k = lid / N, n = lid % N;
    __nv_bfloat16 h, m;
    split2(src[lid], h, m);
    dh[n * K + k] = h;
    dm[n * K + k] = m;
}

__global__ void gather_split_kernel(const float* __restrict__ h2) {
    int cnt = g_cnt;
    int total = cnt * C;
    int stride = gridDim.x * blockDim.x;
    for (int idx = blockIdx.x * blockDim.x + threadIdx.x; idx < total; idx += stride) {
        int i = idx >> 7, c = idx & 127;
        float v = h2[(size_t)g_idx[i] * C + c];
        __nv_bfloat16 h, m;
        split2(v, h, m);
        g_gh[idx] = h; g_gm[idx] = m;
    }
}

// ---------------- 3-stage cp.async + ldmatrix mma GEMM, 128x128 tile ---------
// K-chunk 64, term-sequential (Ah,Bh),(Ah,Bm),(Am,Bh); XOR-swizzled 128B rows.
// smem: 3 x (16KB A + 16KB B) = 98304 + 2KB epi.
// MODE 0: FC1 (epi: relu(v*s+b) -> write h splits bf16 x2)
// MODE 1: FC2 (epi: relu(v*s+b) -> h2 fp32 + fused logit = h2@W3+b3)
// MODE 2: ATT (A = compacted h2 splits; epi: write a fp32 + per-col max)
#define STAGEB 32768
template<int MODE>
__global__ __launch_bounds__(256, 2)
void mma_gemm(const __nv_bfloat16* __restrict__ Ah, const __nv_bfloat16* __restrict__ Am,
              const __nv_bfloat16* __restrict__ Bh, const __nv_bfloat16* __restrict__ Bm,
              const float* __restrict__ scale, const float* __restrict__ bias,
              const float* __restrict__ W3, const float* __restrict__ b3,
              float* __restrict__ logitOut,
              __nv_bfloat16* __restrict__ Oh, __nv_bfloat16* __restrict__ Om,
              float* __restrict__ Of,
              int M, int Ks, int Nn)
{
    extern __shared__ __align__(1024) char sm[];
    char* sEpi = sm + 3 * STAGEB;
    float* s_s  = (float*)sEpi;
    float* s_b  = s_s + 128;
    float* s_w3 = s_b + 128;
    unsigned int* s_red = (unsigned int*)(s_w3 + 128);

    const int tid = threadIdx.x;
    const int wid = tid >> 5, lane = tid & 31;
    const int warpm = wid & 3, warpn = wid >> 2;
    const int gi = lane >> 2, ti = lane & 3;
    const int m0 = blockIdx.x * 128, n0 = blockIdx.y * 128;

    int Meff = M;
    if (MODE == 2) {
        Meff = g_cnt;
        if (m0 >= Meff) return;
    }

    if (tid < 128) {
        if (MODE != 2) { s_s[tid] = scale[n0 + tid]; s_b[tid] = bias[n0 + tid]; }
        if (MODE == 1) { s_w3[tid] = W3[tid]; s_red[tid] = 0u; }
        if (MODE == 2) { s_red[tid] = 0u; }
    }

    float acc[2][8][4];
#pragma unroll
    for (int i = 0; i < 2; i++)
#pragma unroll
        for (int j = 0; j < 8; j++)
#pragma unroll
            for (int q = 0; q < 4; q++) acc[i][j][q] = 0.f;

    // terms: (Ah,Bh), (Ah,Bm), (Am,Bh)
    const int nkc = Ks >> 6;
    const int nchunks = 3 * nkc;
    const uint32_t smu = smem_u32(sm);

    // cp.async geometry: thread -> 4 rows (tid>>3 + i*32), 16B chunk (tid&7)
    const int ldRow = tid >> 3;
    const int ldJ = tid & 7;

    auto issue = [&](int ci) {
        int term = ci / nkc;
        int kc = (ci - term * nkc) << 6;
        const __nv_bfloat16* Ab = (term == 2) ? Am : Ah;
        const __nv_bfloat16* Bb = (term == 1) ? Bm : Bh;
        uint32_t st = smu + (uint32_t)(ci % 3) * STAGEB;
#pragma unroll
        for (int i = 0; i < 4; i++) {
            int row = ldRow + i * 32;
            uint32_t dstoff = (uint32_t)row * 128 + (uint32_t)((ldJ ^ (row & 7)) * 16);
            int gr = m0 + row;
            int ok = (gr < Meff) ? 16 : 0;
            const char* srcA = (const char*)(Ab + (size_t)(ok ? gr : 0) * Ks + kc + ldJ * 8);
            CP16(st + dstoff, srcA, ok);
            const char* srcB = (const char*)(Bb + (size_t)(n0 + row) * Ks + kc + ldJ * 8);
            CP16(st + 16384 + dstoff, srcB, 16);
        }
        CP_COMMIT();
    };

    // ldmatrix per-lane geometry
    // A (per mt): lanes 0-15 -> rows rb+(l&15) @ chunk c0; lanes 16-31 -> same rows @ c0+1
    uint32_t aOff[2], aR7[2];
#pragma unroll
    for (int mt = 0; mt < 2; mt++) {
        int r = warpm * 32 + mt * 16 + (lane & 15);
        aOff[mt] = (uint32_t)r * 128;
        aR7[mt] = (uint32_t)(r & 7);
    }
    const uint32_t aCsel = (uint32_t)(lane >> 4);          // +0 / +1 chunk
    // B (per nt-pair j): lanes 0-7: rows nb+(l&7) @c0; 8-15: same rows @c0+1;
    //                    16-23: rows nb+8+(l&7) @c0; 24-31: @c0+1
    uint32_t bOff[4], bR7[4];
#pragma unroll
    for (int j = 0; j < 4; j++) {
        int r = warpn * 64 + j * 16 + ((lane >> 4) << 3) + (lane & 7);
        bOff[j] = (uint32_t)r * 128;
        bR7[j] = (uint32_t)(r & 7);
    }
    const uint32_t bCsel = (uint32_t)((lane >> 3) & 1);    // +0 / +1 chunk

    issue(0);
    if (nchunks > 1) issue(1);

    for (int ci = 0; ci < nchunks; ci++) {
        if (ci + 1 < nchunks) { CP_WAIT1(); } else { CP_WAIT0(); }
        __syncthreads();
        if (ci + 2 < nchunks) issue(ci + 2);

        uint32_t sAb = smu + (uint32_t)(ci % 3) * STAGEB;
        uint32_t sBb = sAb + 16384;

#pragma unroll
        for (int kk = 0; kk < 64; kk += 16) {
            const uint32_t c0 = (uint32_t)(kk >> 3);
            uint32_t afr[2][4], bfr[8][2];
#pragma unroll
            for (int mt = 0; mt < 2; mt++) {
                uint32_t addr = sAb + aOff[mt] + (((c0 + aCsel) ^ aR7[mt]) << 4);
                LDSM4(afr[mt][0], afr[mt][1], afr[mt][2], afr[mt][3], addr);
            }
#pragma unroll
            for (int j = 0; j < 4; j++) {
                uint32_t addr = sBb + bOff[j] + (((c0 + bCsel) ^ bR7[j]) << 4);
                LDSM4(bfr[2 * j][0], bfr[2 * j][1], bfr[2 * j + 1][0], bfr[2 * j + 1][1], addr);
            }
#pragma unroll
            for (int mt = 0; mt < 2; mt++)
#pragma unroll
                for (int nt = 0; nt < 8; nt++) {
                    asm volatile(
                        "mma.sync.aligned.m16n8k16.row.col.f32.bf16.bf16.f32 "
                        "{%0,%1,%2,%3}, {%4,%5,%6,%7}, {%8,%9}, {%0,%1,%2,%3};"
                        : "+f"(acc[mt][nt][0]), "+f"(acc[mt][nt][1]),
                          "+f"(acc[mt][nt][2]), "+f"(acc[mt][nt][3])
                        : "r"(afr[mt][0]), "r"(afr[mt][1]),
                          "r"(afr[mt][2]), "r"(afr[mt][3]),
                          "r"(bfr[nt][0]), "r"(bfr[nt][1]));
                }
        }
    }

    // ---------------- epilogue ----------------
    float ls[2][2] = {{0.f, 0.f}, {0.f, 0.f}};
    float cmax0[8], cmax1[8];
    if (MODE == 2) {
#pragma unroll
        for (int nt = 0; nt < 8; nt++) { cmax0[nt] = -INFINITY; cmax1[nt] = -INFINITY; }
    }

#pragma unroll
    for (int mt = 0; mt < 2; mt++) {
#pragma unroll
        for (int half = 0; half < 2; half++) {
            int rowL = warpm * 32 + mt * 16 + gi + half * 8;
            int row = m0 + rowL;
            bool vrow = row < Meff;
#pragma unroll
            for (int nt = 0; nt < 8; nt++) {
                int colL = warpn * 64 + nt * 8 + 2 * ti;
                float c0 = acc[mt][nt][2 * half];
                float c1 = acc[mt][nt][2 * half + 1];
                if (MODE != 2) {
                    c0 = fmaxf(fmaf(c0, s_s[colL], s_b[colL]), 0.f);
                    c1 = fmaxf(fmaf(c1, s_s[colL + 1], s_b[colL + 1]), 0.f);
                }
                if (MODE == 0) {
                    if (vrow) {
                        __nv_bfloat16 h0, m0b, h1, m1;
                        split2(c0, h0, m0b);
                        split2(c1, h1, m1);
                        size_t off = (size_t)row * Nn + n0 + colL;
                        *(uint32_t*)(Oh + off) = pk2(h0, h1);
                        *(uint32_t*)(Om + off) = pk2(m0b, m1);
                    }
                } else if (MODE == 1) {
                    if (vrow)
                        *(float2*)(Of + (size_t)row * 128 + colL) = make_float2(c0, c1);
                    ls[mt][half] = fmaf(c0, s_w3[colL], ls[mt][half]);
                    ls[mt][half] = fmaf(c1, s_w3[colL + 1], ls[mt][half]);
                } else {
                    if (vrow) {
                        *(float2*)(Of + (size_t)row * 128 + colL) = make_float2(c0, c1);
                        cmax0[nt] = fmaxf(cmax0[nt], c0);
                        cmax1[nt] = fmaxf(cmax1[nt], c1);
                    }
                }
            }
        }
    }

    if (MODE == 1) {
#pragma unroll
        for (int mt = 0; mt < 2; mt++) {
            atomicAdd((float*)&s_red[warpm * 32 + mt * 16 + gi], ls[mt][0]);
            atomicAdd((float*)&s_red[warpm * 32 + mt * 16 + gi + 8], ls[mt][1]);
        }
        __syncthreads();
        if (tid < 128) {
            int row = m0 + tid;
            if (row < Meff)
                logitOut[row] = __uint_as_float(s_red[tid]) + b3[0];
        }
    } else if (MODE == 2) {
#pragma unroll
        for (int nt = 0; nt < 8; nt++) {
            int colL = warpn * 64 + nt * 8 + 2 * ti;
            if (cmax0[nt] > -INFINITY) atomicMax(&s_red[colL], fkey(cmax0[nt]));
            if (cmax1[nt] > -INFINITY) atomicMax(&s_red[colL + 1], fkey(cmax1[nt]));
        }
        __syncthreads();
        if (tid < 128 && s_red[tid] != 0u)
            atomicMax(&g_maxU[tid], s_red[tid]);
    }
}

// ---------------- mask pass: compact hit points ------------------------------
__global__ void mask_kernel(const float* __restrict__ xyz,
                            const float* __restrict__ pc,
                            const float* __restrict__ pn,
                            const float* __restrict__ pmn,
                            const float* __restrict__ pmx, int M)
{
    __shared__ float s_n0[PP], s_n1[PP], s_n2[PP], s_off[PP];
    __shared__ float s_mn0[PP], s_mn1[PP], s_mx0[PP], s_mx1[PP];
    int t = threadIdx.x;
    if (t < PP) {
        float a0 = pn[t * 3], a1 = pn[t * 3 + 1], a2 = pn[t * 3 + 2];
        s_n0[t] = a0; s_n1[t] = a1; s_n2[t] = a2;
        s_off[t] = pc[t * 3] * a0 + pc[t * 3 + 1] * a1 + pc[t * 3 + 2] * a2;
        s_mn0[t] = pmn[t * 3]; s_mn1[t] = pmn[t * 3 + 1];
        s_mx0[t] = pmx[t * 3]; s_mx1[t] = pmx[t * 3 + 1];
    }
    __syncthreads();
    int n = blockIdx.x * blockDim.x + t;
    if (n >= M) return;
    float x = xyz[n * 3], y = xyz[n * 3 + 1], z = xyz[n * 3 + 2];
    unsigned long long mask = 0ull;
#pragma unroll
    for (int p = 0; p < PP; p++) {
        float proj = x * s_n0[p] + y * s_n1[p] + z * s_n2[p];
        bool hit = (fabsf(proj - s_off[p]) < DIST_TH) &&
                   (x >= s_mn0[p]) && (x < s_mx0[p]) &&
                   (y >= s_mn1[p]) && (y < s_mx1[p]);
        if (hit) mask |= (1ull << p);
    }
    if (mask) {
        int pos = atomicAdd(&g_cnt, 1);
        g_idx[pos] = n;
        g_maskArr[pos] = mask;
    }
}

// ---------------- pooling scatter over compacted points ----------------------
__global__ void pool2_kernel(const float* __restrict__ logit)
{
    __shared__ float s_amax[C];
    if (threadIdx.x < C) s_amax[threadIdx.x] = funkey(g_maxU[threadIdx.x]);
    __syncthreads();
    int cnt = g_cnt;
    int stride = gridDim.x * blockDim.x;
    for (int i = blockIdx.x * blockDim.x + threadIdx.x; i < cnt; i += stride) {
        int n = g_idx[i];
        unsigned long long mask = g_maskArr[i];
        bool on = logit[n] > 0.0f;
        float* numB = on ? g_num_on : g_num_off;
        float* denB = on ? g_den_on : g_den_off;
        const float* ar = g_a + (size_t)i * C;
        const float* hr = g_h2 + (size_t)n * C;
        for (int c = 0; c < C; c += 4) {
            float4 a4 = *(const float4*)(ar + c);
            float4 h4 = *(const float4*)(hr + c);
            float e0 = expf(a4.x - s_amax[c + 0]);
            float e1 = expf(a4.y - s_amax[c + 1]);
            float e2 = expf(a4.z - s_amax[c + 2]);
            float e3 = expf(a4.w - s_amax[c + 3]);
            unsigned long long mm = mask;
            while (mm) {
                int p = __ffsll(mm) - 1;
                mm &= mm - 1;
                float* dn = denB + p * C + c;
                float* nm = numB + p * C + c;
                atomicAdd(dn + 0, e0); atomicAdd(dn + 1, e1);
                atomicAdd(dn + 2, e2); atomicAdd(dn + 3, e3);
                atomicAdd(nm + 0, e0 * h4.x); atomicAdd(nm + 1, e1 * h4.y);
                atomicAdd(nm + 2, e2 * h4.z); atomicAdd(nm + 3, e3 * h4.w);
            }
        }
    }
}

// ---------------- finalize: agg -> relu(agg@Wm+bm), concat ori --------------
__global__ void finalize_kernel(const float* __restrict__ Wm,
                                const float* __restrict__ bm,
                                const float* __restrict__ pc,
                                const float* __restrict__ pn,
                                const float* __restrict__ pmn,
                                const float* __restrict__ pmx,
                                float* __restrict__ out, int M)
{
    int p = blockIdx.x;     // 64
    int c = threadIdx.x;    // 128
    __shared__ float aggOn[C], aggOff[C];
    aggOn[c]  = g_num_on [p * C + c] / (g_den_on [p * C + c] + 1e-9f);
    aggOff[c] = g_num_off[p * C + c] / (g_den_off[p * C + c] + 1e-9f);
    __syncthreads();
    float so = 0.f, sf = 0.f;
#pragma unroll 8
    for (int k = 0; k < C; k++) {
        float w = Wm[k * C + c];
        so = fmaf(aggOn[k], w, so);
        sf = fmaf(aggOff[k], w, sf);
    }
    float bb = bm[c];
    float* onRow  = out + M + (size_t)p * (C + 12);
    float* offRow = out + M + (size_t)PP * (C + 12) + (size_t)p * (C + 12);
    onRow[c]  = fmaxf(so + bb, 0.f);
    offRow[c] = fmaxf(sf + bb, 0.f);
    if (c < 12) {
        int axis = c % 3, grp = c / 3;
        const float* src = (grp == 0) ? pc : (grp == 1) ? pn : (grp == 2) ? pmn : pmx;
        float v = src[p * 3 + axis];
        onRow[C + c] = v;
        offRow[C + c] = v;
    }
}

// ---------------- launch ----------------
extern "C" void kernel_launch(void* const* d_in, const int* in_sizes, int n_in,
                              void* d_out, int out_size)
{
    const float* feature = (const float*)d_in[0];
    const float* xyz     = (const float*)d_in[1];
    const float* pc      = (const float*)d_in[2];
    const float* pn      = (const float*)d_in[3];
    const float* pmn     = (const float*)d_in[4];
    const float* pmx     = (const float*)d_in[5];
    const float* W1      = (const float*)d_in[6];
    const float* s1      = (const float*)d_in[7];
    const float* b1      = (const float*)d_in[8];
    const float* W2      = (const float*)d_in[9];
    const float* s2      = (const float*)d_in[10];
    const float* b2      = (const float*)d_in[11];
    const float* W3      = (const float*)d_in[12];
    const float* b3      = (const float*)d_in[13];
    const float* Wa      = (const float*)d_in[14];
    const float* Wm      = (const float*)d_in[15];
    const float* bm      = (const float*)d_in[16];

    int M = in_sizes[1] / 3;            // N = 100000
    float* out = (float*)d_out;

    __nv_bfloat16 *fh, *fm, *hh, *hm, *gh, *gm;
    __nv_bfloat16 *w1h, *w1m, *w2h, *w2m, *wah, *wam;
    float *h2P, *aP;
    cudaGetSymbolAddress((void**)&fh, g_fh);
    cudaGetSymbolAddress((void**)&fm, g_fm);
    cudaGetSymbolAddress((void**)&hh, g_hh);
    cudaGetSymbolAddress((void**)&hm, g_hm);
    cudaGetSymbolAddress((void**)&gh, g_gh);
    cudaGetSymbolAddress((void**)&gm, g_gm);
    cudaGetSymbolAddress((void**)&w1h, g_w1h);
    cudaGetSymbolAddress((void**)&w1m, g_w1m);
    cudaGetSymbolAddress((void**)&w2h, g_w2h);
    cudaGetSymbolAddress((void**)&w2m, g_w2m);
    cudaGetSymbolAddress((void**)&wah, g_wah);
    cudaGetSymbolAddress((void**)&wam, g_wam);
    cudaGetSymbolAddress((void**)&h2P, g_h2);
    cudaGetSymbolAddress((void**)&aP,  g_a);

    const int SMEM = 3 * STAGEB + 2048;    // 100352
    cudaFuncSetAttribute(mma_gemm<0>, cudaFuncAttributeMaxDynamicSharedMemorySize, SMEM);
    cudaFuncSetAttribute(mma_gemm<1>, cudaFuncAttributeMaxDynamicSharedMemorySize, SMEM);
    cudaFuncSetAttribute(mma_gemm<2>, cudaFuncAttributeMaxDynamicSharedMemorySize, SMEM);

    int gx = (M + 127) / 128;           // 782

    init_kernel<<<32, 256>>>();
    mask_kernel<<<(M + 255) / 256, 256>>>(xyz, pc, pn, pmn, pmx, M);
    split_feat_kernel<<<(M * C / 4 + 255) / 256, 256>>>(feature, fh, fm, M * C / 4);
    split_w_all_kernel<<<(2 * C * C2 + C * C + 255) / 256, 256>>>(W1, W2, Wa);

    // FC1: h = relu((feature@W1)*s1+b1) -> h splits   [M,128]x[128,256]
    mma_gemm<0><<<dim3(gx, 2), 256, SMEM>>>(fh, fm, w1h, w1m,
                                            s1, b1, nullptr, nullptr, nullptr,
                                            hh, hm, nullptr, M, C, C2);
    // FC2: h2 = relu((h@W2)*s2+b2) fp32 + fused logit -> out[0..M)
    mma_gemm<1><<<dim3(gx, 1), 256, SMEM>>>(hh, hm, w2h, w2m,
                                            s2, b2, W3, b3, out,
                                            nullptr, nullptr, h2P, M, C2, C);
    // gather+split h2 rows for masked points
    gather_split_kernel<<<256, 256>>>(h2P);
    // ATT: a = h2_masked @ Wa + per-channel max over masked rows
    mma_gemm<2><<<dim3(gx, 1), 256, SMEM>>>(gh, gm, wah, wam,
                                            nullptr, nullptr, nullptr, nullptr, nullptr,
                                            nullptr, nullptr, aP, M, C, C);
    // sparse masked softmax pooling scatter
    pool2_kernel<<<256, 256>>>(out);
    // tiny per-plane GEMM + ori concat
    finalize_kernel<<<PP, 128>>>(Wm, bm, pc, pn, pmn, pmx, out, M);
}